// round 1
// baseline (speedup 1.0000x reference)
#include <cuda_runtime.h>

// EA-LSTM fused persistent kernel.
// B=1024, T=365, Dd=32, Ds=27, H=256, 3H=768, O=1.
// Grid: 128 CTAs x 256 threads. Each CTA owns M=8 batch elements for the
// whole sequence (no inter-CTA communication). Thread j owns gate columns
// (j, 256+j, 512+j) i.e. f_j/o_j/g_j, for all 8 batch elements; c and
// i_gate live in registers; h lives in SMEM transposed [k][m] for broadcast
// reads. Accumulation uses Blackwell packed fp32x2 FMA (bit-exact fp32).
// W_hh streams from L2 each step via __ldcg (bypass L1); W_ih stays hot in L1.

#define B_      1024
#define T_      365
#define DD      32
#define DS      27
#define H_      256
#define G3      768
#define M_      8
#define THREADS 256
#define CTAS    (B_ / M_)      // 128
#define HS_STRIDE 10           // padded h stride (floats): 8B aligned, 2-way max bank conflict

#ifndef USE_F32X2
#define USE_F32X2 1
#endif

typedef unsigned long long u64;

__device__ __forceinline__ u64 pack2(float lo, float hi) {
    u64 r; asm("mov.b64 %0, {%1, %2};" : "=l"(r) : "f"(lo), "f"(hi)); return r;
}
__device__ __forceinline__ void unpack2(u64 v, float& lo, float& hi) {
    asm("mov.b64 {%0, %1}, %2;" : "=f"(lo), "=f"(hi) : "l"(v));
}
#if USE_F32X2
__device__ __forceinline__ void fma2(u64& d, u64 a, u64 b) {
    asm("fma.rn.f32x2 %0, %1, %2, %0;" : "+l"(d) : "l"(a), "l"(b));
}
#else
__device__ __forceinline__ void fma2(u64& d, u64 a, u64 b) {
    float dl, dh, al, ah, bl, bh;
    unpack2(d, dl, dh); unpack2(a, al, ah); unpack2(b, bl, bh);
    dl = fmaf(al, bl, dl); dh = fmaf(ah, bh, dh);
    d = pack2(dl, dh);
}
#endif

__device__ __forceinline__ float sigmoidf_(float x) {
    return __fdividef(1.0f, 1.0f + __expf(-x));
}
__device__ __forceinline__ float tanhf_(float x) {
    float e = __expf(-2.0f * x);
    return __fdividef(1.0f - e, 1.0f + e);
}

__global__ void __launch_bounds__(THREADS, 1)
ealstm_kernel(const float* __restrict__ xd,      // [B, T, DD]
              const float* __restrict__ xs,      // [B, DS]
              const float* __restrict__ Wih,     // [DD, 3H]
              const float* __restrict__ Whh,     // [H, 3H]
              const float* __restrict__ Wsh,     // [DS, H]
              const float* __restrict__ bias,    // [3H]
              const float* __restrict__ bias_s,  // [H]
              const float* __restrict__ Wout,    // [H, 1]
              const float* __restrict__ bout,    // [1]
              float* __restrict__ out)           // [B, T, 1]
{
    __shared__ float h_s[H_ * HS_STRIDE];   // h transposed: h_s[k*HS_STRIDE + m]
    __shared__ float x_s[DD * M_];          // x_t transposed: x_s[k*M_ + m]

    const int j    = threadIdx.x;           // gate/h index 0..255
    const int b0   = blockIdx.x * M_;
    const int lane = j & 31;
    const int warp = j >> 5;                // also the batch element m for the out-dot

    // zero initial hidden state
    for (int idx = j; idx < H_ * HS_STRIDE; idx += THREADS) h_s[idx] = 0.0f;

    // stage x_t for t = 0
    {
        const int m = j >> 5, k = j & 31;
        x_s[k * M_ + m] = xd[((size_t)(b0 + m) * T_ + 0) * DD + k];
    }

    // per-thread gate biases
    const float bf = bias[j], bo = bias[H_ + j], bg = bias[2 * H_ + j];

    // entity-aware input gate: ig[m] = sigmoid(x_static[b0+m] . W_sh[:, j] + bias_s[j])
    float ig[M_];
    {
        float s[M_];
        #pragma unroll
        for (int m = 0; m < M_; m++) s[m] = bias_s[j];
        #pragma unroll 1
        for (int k = 0; k < DS; k++) {
            const float w = Wsh[k * H_ + j];
            #pragma unroll
            for (int m = 0; m < M_; m++)
                s[m] = fmaf(xs[(b0 + m) * DS + k], w, s[m]);
        }
        #pragma unroll
        for (int m = 0; m < M_; m++) ig[m] = sigmoidf_(s[m]);
    }

    // per-lane output weights for the warp-level out-dot (loaded once)
    float wout[8];
    #pragma unroll
    for (int q = 0; q < 8; q++) wout[q] = Wout[lane + 32 * q];
    const float b_out0 = bout[0];

    float c[M_];
    #pragma unroll
    for (int m = 0; m < M_; m++) c[m] = 0.0f;

    __syncthreads();

    for (int t = 0; t < T_; t++) {
        // ---- gate accumulation: gates = bias + x_t @ W_ih + h @ W_hh ----
        u64 aF[4], aO[4], aG[4];
        {
            const u64 bf2 = pack2(bf, bf), bo2 = pack2(bo, bo), bg2 = pack2(bg, bg);
            #pragma unroll
            for (int p = 0; p < 4; p++) { aF[p] = bf2; aO[p] = bo2; aG[p] = bg2; }
        }

        // x contribution (W_ih stays L1-resident: default cached loads)
        #pragma unroll 4
        for (int k = 0; k < DD; k++) {
            const float* wr = Wih + k * G3 + j;
            const float wf = __ldg(wr), wo = __ldg(wr + H_), wg = __ldg(wr + 2 * H_);
            const u64 wf2 = pack2(wf, wf), wo2 = pack2(wo, wo), wg2 = pack2(wg, wg);
            const u64* xp = (const u64*)(x_s + k * M_);
            #pragma unroll
            for (int p = 0; p < 4; p++) {
                const u64 xv = xp[p];
                fma2(aF[p], wf2, xv);
                fma2(aO[p], wo2, xv);
                fma2(aG[p], wg2, xv);
            }
        }

        // h contribution (W_hh: L2-only loads, don't thrash L1)
        #pragma unroll 4
        for (int k = 0; k < H_; k++) {
            const float* wr = Whh + k * G3 + j;
            const float wf = __ldcg(wr), wo = __ldcg(wr + H_), wg = __ldcg(wr + 2 * H_);
            const u64 wf2 = pack2(wf, wf), wo2 = pack2(wo, wo), wg2 = pack2(wg, wg);
            const float* hb = h_s + k * HS_STRIDE;
            #pragma unroll
            for (int p = 0; p < 4; p++) {
                const u64 hv = *(const u64*)(hb + 2 * p);
                fma2(aF[p], wf2, hv);
                fma2(aO[p], wo2, hv);
                fma2(aG[p], wg2, hv);
            }
        }

        __syncthreads();   // all reads of h_s / x_s for step t are done

        // ---- state update ----
        float hnew[M_];
        #pragma unroll
        for (int p = 0; p < 4; p++) {
            float f0, f1, o0, o1, g0, g1;
            unpack2(aF[p], f0, f1);
            unpack2(aO[p], o0, o1);
            unpack2(aG[p], g0, g1);
            const int m0 = 2 * p, m1 = 2 * p + 1;
            c[m0] = sigmoidf_(f0) * c[m0] + ig[m0] * tanhf_(g0);
            c[m1] = sigmoidf_(f1) * c[m1] + ig[m1] * tanhf_(g1);
            hnew[m0] = sigmoidf_(o0) * tanhf_(c[m0]);
            hnew[m1] = sigmoidf_(o1) * tanhf_(c[m1]);
        }
        #pragma unroll
        for (int m = 0; m < M_; m++) h_s[j * HS_STRIDE + m] = hnew[m];

        // stage x for t+1
        if (t + 1 < T_) {
            const int m = j >> 5, k = j & 31;
            x_s[k * M_ + m] = xd[((size_t)(b0 + m) * T_ + (t + 1)) * DD + k];
        }

        __syncthreads();   // h_s(t) and x_s(t+1) published

        // ---- output: out[b0+warp][t] = h . W_out + b_out (warp `w` owns m=w) ----
        {
            float acc = 0.0f;
            #pragma unroll
            for (int q = 0; q < 8; q++) {
                const int jj = lane + 32 * q;
                acc = fmaf(h_s[jj * HS_STRIDE + warp], wout[q], acc);
            }
            #pragma unroll
            for (int off = 16; off > 0; off >>= 1)
                acc += __shfl_down_sync(0xffffffffu, acc, off);
            if (lane == 0)
                out[(size_t)(b0 + warp) * T_ + t] = acc + b_out0;
        }
        // no sync needed here: next iteration only READS h_s/x_s until its own
        // first __syncthreads(), after which writes are allowed again.
    }
}

extern "C" void kernel_launch(void* const* d_in, const int* in_sizes, int n_in,
                              void* d_out, int out_size) {
    const float* xd     = (const float*)d_in[0];  // x_dynamic [1024,365,32]
    const float* xs     = (const float*)d_in[1];  // x_static  [1024,27]
    const float* Wih    = (const float*)d_in[2];  // [32,768]
    const float* Whh    = (const float*)d_in[3];  // [256,768]
    const float* Wsh    = (const float*)d_in[4];  // [27,256]
    const float* bias   = (const float*)d_in[5];  // [768]
    const float* bias_s = (const float*)d_in[6];  // [256]
    const float* Wout   = (const float*)d_in[7];  // [256,1]
    const float* bout   = (const float*)d_in[8];  // [1]
    float* out = (float*)d_out;                   // [1024,365,1]

    ealstm_kernel<<<CTAS, THREADS>>>(xd, xs, Wih, Whh, Wsh, bias, bias_s,
                                     Wout, bout, out);
}

// round 2
// speedup vs baseline: 1.5377x; 1.5377x over previous
#include <cuda_runtime.h>

// EA-LSTM fused persistent kernel, round 2: split-k across 2 warp groups.
// B=1024, T=365, Dd=32, Ds=27, H=256, 3H=768, O=1.
// Grid: 128 CTAs x 512 threads. CTA owns M=8 batch elems for the whole
// sequence. Logical column j in [0,256): thread j (group 0) and thread
// 256+j (group 1) split the k-reduction of gates f_j/o_j/g_j:
//   group 0: bias + x_t @ W_ih + h[k=0..111]   @ W_hh
//   group 1:                    h[k=112..255]  @ W_hh  -> partials via SMEM
// Group 0 combines, applies the nonlinearities, updates c/h and does the
// scalar output dot; group 1 concurrently stages x_{t+1}.
// All accumulation in Blackwell packed fp32x2 (bit-exact fp32).

#define B_      1024
#define T_      365
#define DD      32
#define DS      27
#define H_      256
#define G3      768
#define M_      8
#define THREADS 512
#define CTAS    (B_ / M_)      // 128
#define HS_STRIDE 10           // padded h stride (floats)
#define PS_STRIDE 13           // padded partial stride (u64 per column)
#define KSPLIT  112            // group0 h-range [0,112), group1 [112,256)

typedef unsigned long long u64;

__device__ __forceinline__ u64 pack2(float lo, float hi) {
    u64 r; asm("mov.b64 %0, {%1, %2};" : "=l"(r) : "f"(lo), "f"(hi)); return r;
}
__device__ __forceinline__ void unpack2(u64 v, float& lo, float& hi) {
    asm("mov.b64 {%0, %1}, %2;" : "=f"(lo), "=f"(hi) : "l"(v));
}
__device__ __forceinline__ void fma2(u64& d, u64 a, u64 b) {
    asm("fma.rn.f32x2 %0, %1, %2, %0;" : "+l"(d) : "l"(a), "l"(b));
}
__device__ __forceinline__ void add2(u64& d, u64 a) {
    asm("add.rn.f32x2 %0, %0, %1;" : "+l"(d) : "l"(a));
}

__device__ __forceinline__ float sigmoidf_(float x) {
    return __fdividef(1.0f, 1.0f + __expf(-x));
}
__device__ __forceinline__ float tanhf_(float x) {
    float e = __expf(-2.0f * x);
    return __fdividef(1.0f - e, 1.0f + e);
}

__global__ void __launch_bounds__(THREADS, 1)
ealstm_kernel(const float* __restrict__ xd,      // [B, T, DD]
              const float* __restrict__ xs,      // [B, DS]
              const float* __restrict__ Wih,     // [DD, 3H]
              const float* __restrict__ Whh,     // [H, 3H]
              const float* __restrict__ Wsh,     // [DS, H]
              const float* __restrict__ bias,    // [3H]
              const float* __restrict__ bias_s,  // [H]
              const float* __restrict__ Wout,    // [H, 1]
              const float* __restrict__ bout,    // [1]
              float* __restrict__ out)           // [B, T, 1]
{
    __shared__ float h_s[H_ * HS_STRIDE];   // h transposed: h_s[k*HS_STRIDE + m]
    __shared__ float x_s[DD * M_];          // x_t transposed: x_s[k*M_ + m]
    __shared__ u64   p_s[H_ * PS_STRIDE];   // group-1 partial gate sums

    const int j    = threadIdx.x;
    const int grp  = j >> 8;                // 0 or 1
    const int col  = j & 255;               // gate/h column
    const int b0   = blockIdx.x * M_;
    const int lane = j & 31;
    const int warp = j >> 5;                // warps 0..7 (grp 0) do the out-dot

    // zero initial hidden state
    for (int idx = j; idx < H_ * HS_STRIDE; idx += THREADS) h_s[idx] = 0.0f;

    // stage x_t for t = 0 (group 1's 256 threads)
    if (grp == 1) {
        const int m = col >> 5, k = col & 31;
        x_s[k * M_ + m] = xd[((size_t)(b0 + m) * T_ + 0) * DD + k];
    }

    // per-thread gate biases (group 0 seeds accumulators with them)
    float bf = 0.0f, bo = 0.0f, bg = 0.0f;
    if (grp == 0) { bf = bias[col]; bo = bias[H_ + col]; bg = bias[2 * H_ + col]; }

    // entity-aware input gate (group 0 only)
    float ig[M_];
    if (grp == 0) {
        float s[M_];
        #pragma unroll
        for (int m = 0; m < M_; m++) s[m] = bias_s[col];
        #pragma unroll 1
        for (int k = 0; k < DS; k++) {
            const float w = Wsh[k * H_ + col];
            #pragma unroll
            for (int m = 0; m < M_; m++)
                s[m] = fmaf(xs[(b0 + m) * DS + k], w, s[m]);
        }
        #pragma unroll
        for (int m = 0; m < M_; m++) ig[m] = sigmoidf_(s[m]);
    }

    // per-lane output weights for the warp-level out-dot
    float wout[8];
    #pragma unroll
    for (int q = 0; q < 8; q++) wout[q] = Wout[lane + 32 * q];
    const float b_out0 = bout[0];

    float c[M_];
    #pragma unroll
    for (int m = 0; m < M_; m++) c[m] = 0.0f;

    __syncthreads();

    for (int t = 0; t < T_; t++) {
        u64 aF[4], aO[4], aG[4];

        if (grp == 0) {
            // seed with bias
            const u64 bf2 = pack2(bf, bf), bo2 = pack2(bo, bo), bg2 = pack2(bg, bg);
            #pragma unroll
            for (int p = 0; p < 4; p++) { aF[p] = bf2; aO[p] = bo2; aG[p] = bg2; }

            // x contribution (W_ih stays L1-resident)
            #pragma unroll 4
            for (int k = 0; k < DD; k++) {
                const float* wr = Wih + k * G3 + col;
                const float wf = __ldg(wr), wo = __ldg(wr + H_), wg = __ldg(wr + 2 * H_);
                const u64 wf2 = pack2(wf, wf), wo2 = pack2(wo, wo), wg2 = pack2(wg, wg);
                const u64* xp = (const u64*)(x_s + k * M_);
                #pragma unroll
                for (int p = 0; p < 4; p++) {
                    const u64 xv = xp[p];
                    fma2(aF[p], wf2, xv);
                    fma2(aO[p], wo2, xv);
                    fma2(aG[p], wg2, xv);
                }
            }
            // h contribution, k in [0, KSPLIT)
            #pragma unroll 4
            for (int k = 0; k < KSPLIT; k++) {
                const float* wr = Whh + k * G3 + col;
                const float wf = __ldcg(wr), wo = __ldcg(wr + H_), wg = __ldcg(wr + 2 * H_);
                const u64 wf2 = pack2(wf, wf), wo2 = pack2(wo, wo), wg2 = pack2(wg, wg);
                const float* hb = h_s + k * HS_STRIDE;
                #pragma unroll
                for (int p = 0; p < 4; p++) {
                    const u64 hv = *(const u64*)(hb + 2 * p);
                    fma2(aF[p], wf2, hv);
                    fma2(aO[p], wo2, hv);
                    fma2(aG[p], wg2, hv);
                }
            }
        } else {
            #pragma unroll
            for (int p = 0; p < 4; p++) { aF[p] = 0ull; aO[p] = 0ull; aG[p] = 0ull; }

            // h contribution, k in [KSPLIT, 256)
            #pragma unroll 4
            for (int k = KSPLIT; k < H_; k++) {
                const float* wr = Whh + k * G3 + col;
                const float wf = __ldcg(wr), wo = __ldcg(wr + H_), wg = __ldcg(wr + 2 * H_);
                const u64 wf2 = pack2(wf, wf), wo2 = pack2(wo, wo), wg2 = pack2(wg, wg);
                const float* hb = h_s + k * HS_STRIDE;
                #pragma unroll
                for (int p = 0; p < 4; p++) {
                    const u64 hv = *(const u64*)(hb + 2 * p);
                    fma2(aF[p], wf2, hv);
                    fma2(aO[p], wo2, hv);
                    fma2(aG[p], wg2, hv);
                }
            }
            // publish partials
            u64* pp = p_s + col * PS_STRIDE;
            #pragma unroll
            for (int p = 0; p < 4; p++) {
                pp[p]     = aF[p];
                pp[4 + p] = aO[p];
                pp[8 + p] = aG[p];
            }
        }

        __syncthreads();   // partials published; all h_s/x_s reads of step t done

        if (grp == 0) {
            // combine partials
            const u64* pp = p_s + col * PS_STRIDE;
            #pragma unroll
            for (int p = 0; p < 4; p++) {
                add2(aF[p], pp[p]);
                add2(aO[p], pp[4 + p]);
                add2(aG[p], pp[8 + p]);
            }
            // state update
            float hnew[M_];
            #pragma unroll
            for (int p = 0; p < 4; p++) {
                float f0, f1, o0, o1, g0, g1;
                unpack2(aF[p], f0, f1);
                unpack2(aO[p], o0, o1);
                unpack2(aG[p], g0, g1);
                const int m0 = 2 * p, m1 = 2 * p + 1;
                c[m0] = sigmoidf_(f0) * c[m0] + ig[m0] * tanhf_(g0);
                c[m1] = sigmoidf_(f1) * c[m1] + ig[m1] * tanhf_(g1);
                hnew[m0] = sigmoidf_(o0) * tanhf_(c[m0]);
                hnew[m1] = sigmoidf_(o1) * tanhf_(c[m1]);
            }
            #pragma unroll
            for (int m = 0; m < M_; m++) h_s[col * HS_STRIDE + m] = hnew[m];
        } else {
            // stage x for t+1
            if (t + 1 < T_) {
                const int m = col >> 5, k = col & 31;
                x_s[k * M_ + m] = xd[((size_t)(b0 + m) * T_ + (t + 1)) * DD + k];
            }
        }

        __syncthreads();   // h_s(t) and x_s(t+1) published

        // output: out[b0+w][t] = h . W_out + b_out  (group-0 warp w owns m=w)
        if (grp == 0) {
            float acc = 0.0f;
            #pragma unroll
            for (int q = 0; q < 8; q++) {
                const int jj = lane + 32 * q;
                acc = fmaf(h_s[jj * HS_STRIDE + warp], wout[q], acc);
            }
            #pragma unroll
            for (int off = 16; off > 0; off >>= 1)
                acc += __shfl_down_sync(0xffffffffu, acc, off);
            if (lane == 0)
                out[(size_t)(b0 + warp) * T_ + t] = acc + b_out0;
        }
        // next iteration's h_s/p_s writes are fenced by its own first sync
    }
}

extern "C" void kernel_launch(void* const* d_in, const int* in_sizes, int n_in,
                              void* d_out, int out_size) {
    const float* xd     = (const float*)d_in[0];  // x_dynamic [1024,365,32]
    const float* xs     = (const float*)d_in[1];  // x_static  [1024,27]
    const float* Wih    = (const float*)d_in[2];  // [32,768]
    const float* Whh    = (const float*)d_in[3];  // [256,768]
    const float* Wsh    = (const float*)d_in[4];  // [27,256]
    const float* bias   = (const float*)d_in[5];  // [768]
    const float* bias_s = (const float*)d_in[6];  // [256]
    const float* Wout   = (const float*)d_in[7];  // [256,1]
    const float* bout   = (const float*)d_in[8];  // [1]
    float* out = (float*)d_out;                   // [1024,365,1]

    ealstm_kernel<<<CTAS, THREADS>>>(xd, xs, Wih, Whh, Wsh, bias, bias_s,
                                     Wout, bout, out);
}

// round 3
// speedup vs baseline: 1.5383x; 1.0004x over previous
#include <cuda_runtime.h>

// EA-LSTM fused persistent kernel, round 2: split-k across 2 warp groups.
// B=1024, T=365, Dd=32, Ds=27, H=256, 3H=768, O=1.
// Grid: 128 CTAs x 512 threads. CTA owns M=8 batch elems for the whole
// sequence. Logical column j in [0,256): thread j (group 0) and thread
// 256+j (group 1) split the k-reduction of gates f_j/o_j/g_j:
//   group 0: bias + x_t @ W_ih + h[k=0..111]   @ W_hh
//   group 1:                    h[k=112..255]  @ W_hh  -> partials via SMEM
// Group 0 combines, applies the nonlinearities, updates c/h and does the
// scalar output dot; group 1 concurrently stages x_{t+1}.
// All accumulation in Blackwell packed fp32x2 (bit-exact fp32).

#define B_      1024
#define T_      365
#define DD      32
#define DS      27
#define H_      256
#define G3      768
#define M_      8
#define THREADS 512
#define CTAS    (B_ / M_)      // 128
#define HS_STRIDE 10           // padded h stride (floats)
#define PS_STRIDE 13           // padded partial stride (u64 per column)
#define KSPLIT  112            // group0 h-range [0,112), group1 [112,256)

typedef unsigned long long u64;

__device__ __forceinline__ u64 pack2(float lo, float hi) {
    u64 r; asm("mov.b64 %0, {%1, %2};" : "=l"(r) : "f"(lo), "f"(hi)); return r;
}
__device__ __forceinline__ void unpack2(u64 v, float& lo, float& hi) {
    asm("mov.b64 {%0, %1}, %2;" : "=f"(lo), "=f"(hi) : "l"(v));
}
__device__ __forceinline__ void fma2(u64& d, u64 a, u64 b) {
    asm("fma.rn.f32x2 %0, %1, %2, %0;" : "+l"(d) : "l"(a), "l"(b));
}
__device__ __forceinline__ void add2(u64& d, u64 a) {
    asm("add.rn.f32x2 %0, %0, %1;" : "+l"(d) : "l"(a));
}

__device__ __forceinline__ float sigmoidf_(float x) {
    return __fdividef(1.0f, 1.0f + __expf(-x));
}
__device__ __forceinline__ float tanhf_(float x) {
    float e = __expf(-2.0f * x);
    return __fdividef(1.0f - e, 1.0f + e);
}

__global__ void __launch_bounds__(THREADS, 1)
ealstm_kernel(const float* __restrict__ xd,      // [B, T, DD]
              const float* __restrict__ xs,      // [B, DS]
              const float* __restrict__ Wih,     // [DD, 3H]
              const float* __restrict__ Whh,     // [H, 3H]
              const float* __restrict__ Wsh,     // [DS, H]
              const float* __restrict__ bias,    // [3H]
              const float* __restrict__ bias_s,  // [H]
              const float* __restrict__ Wout,    // [H, 1]
              const float* __restrict__ bout,    // [1]
              float* __restrict__ out)           // [B, T, 1]
{
    __shared__ float h_s[H_ * HS_STRIDE];   // h transposed: h_s[k*HS_STRIDE + m]
    __shared__ float x_s[DD * M_];          // x_t transposed: x_s[k*M_ + m]
    __shared__ u64   p_s[H_ * PS_STRIDE];   // group-1 partial gate sums

    const int j    = threadIdx.x;
    const int grp  = j >> 8;                // 0 or 1
    const int col  = j & 255;               // gate/h column
    const int b0   = blockIdx.x * M_;
    const int lane = j & 31;
    const int warp = j >> 5;                // warps 0..7 (grp 0) do the out-dot

    // zero initial hidden state
    for (int idx = j; idx < H_ * HS_STRIDE; idx += THREADS) h_s[idx] = 0.0f;

    // stage x_t for t = 0 (group 1's 256 threads)
    if (grp == 1) {
        const int m = col >> 5, k = col & 31;
        x_s[k * M_ + m] = xd[((size_t)(b0 + m) * T_ + 0) * DD + k];
    }

    // per-thread gate biases (group 0 seeds accumulators with them)
    float bf = 0.0f, bo = 0.0f, bg = 0.0f;
    if (grp == 0) { bf = bias[col]; bo = bias[H_ + col]; bg = bias[2 * H_ + col]; }

    // entity-aware input gate (group 0 only)
    float ig[M_];
    if (grp == 0) {
        float s[M_];
        #pragma unroll
        for (int m = 0; m < M_; m++) s[m] = bias_s[col];
        #pragma unroll 1
        for (int k = 0; k < DS; k++) {
            const float w = Wsh[k * H_ + col];
            #pragma unroll
            for (int m = 0; m < M_; m++)
                s[m] = fmaf(xs[(b0 + m) * DS + k], w, s[m]);
        }
        #pragma unroll
        for (int m = 0; m < M_; m++) ig[m] = sigmoidf_(s[m]);
    }

    // per-lane output weights for the warp-level out-dot
    float wout[8];
    #pragma unroll
    for (int q = 0; q < 8; q++) wout[q] = Wout[lane + 32 * q];
    const float b_out0 = bout[0];

    float c[M_];
    #pragma unroll
    for (int m = 0; m < M_; m++) c[m] = 0.0f;

    __syncthreads();

    for (int t = 0; t < T_; t++) {
        u64 aF[4], aO[4], aG[4];

        if (grp == 0) {
            // seed with bias
            const u64 bf2 = pack2(bf, bf), bo2 = pack2(bo, bo), bg2 = pack2(bg, bg);
            #pragma unroll
            for (int p = 0; p < 4; p++) { aF[p] = bf2; aO[p] = bo2; aG[p] = bg2; }

            // x contribution (W_ih stays L1-resident)
            #pragma unroll 4
            for (int k = 0; k < DD; k++) {
                const float* wr = Wih + k * G3 + col;
                const float wf = __ldg(wr), wo = __ldg(wr + H_), wg = __ldg(wr + 2 * H_);
                const u64 wf2 = pack2(wf, wf), wo2 = pack2(wo, wo), wg2 = pack2(wg, wg);
                const u64* xp = (const u64*)(x_s + k * M_);
                #pragma unroll
                for (int p = 0; p < 4; p++) {
                    const u64 xv = xp[p];
                    fma2(aF[p], wf2, xv);
                    fma2(aO[p], wo2, xv);
                    fma2(aG[p], wg2, xv);
                }
            }
            // h contribution, k in [0, KSPLIT)
            #pragma unroll 4
            for (int k = 0; k < KSPLIT; k++) {
                const float* wr = Whh + k * G3 + col;
                const float wf = __ldcg(wr), wo = __ldcg(wr + H_), wg = __ldcg(wr + 2 * H_);
                const u64 wf2 = pack2(wf, wf), wo2 = pack2(wo, wo), wg2 = pack2(wg, wg);
                const float* hb = h_s + k * HS_STRIDE;
                #pragma unroll
                for (int p = 0; p < 4; p++) {
                    const u64 hv = *(const u64*)(hb + 2 * p);
                    fma2(aF[p], wf2, hv);
                    fma2(aO[p], wo2, hv);
                    fma2(aG[p], wg2, hv);
                }
            }
        } else {
            #pragma unroll
            for (int p = 0; p < 4; p++) { aF[p] = 0ull; aO[p] = 0ull; aG[p] = 0ull; }

            // h contribution, k in [KSPLIT, 256)
            #pragma unroll 4
            for (int k = KSPLIT; k < H_; k++) {
                const float* wr = Whh + k * G3 + col;
                const float wf = __ldcg(wr), wo = __ldcg(wr + H_), wg = __ldcg(wr + 2 * H_);
                const u64 wf2 = pack2(wf, wf), wo2 = pack2(wo, wo), wg2 = pack2(wg, wg);
                const float* hb = h_s + k * HS_STRIDE;
                #pragma unroll
                for (int p = 0; p < 4; p++) {
                    const u64 hv = *(const u64*)(hb + 2 * p);
                    fma2(aF[p], wf2, hv);
                    fma2(aO[p], wo2, hv);
                    fma2(aG[p], wg2, hv);
                }
            }
            // publish partials
            u64* pp = p_s + col * PS_STRIDE;
            #pragma unroll
            for (int p = 0; p < 4; p++) {
                pp[p]     = aF[p];
                pp[4 + p] = aO[p];
                pp[8 + p] = aG[p];
            }
        }

        __syncthreads();   // partials published; all h_s/x_s reads of step t done

        if (grp == 0) {
            // combine partials
            const u64* pp = p_s + col * PS_STRIDE;
            #pragma unroll
            for (int p = 0; p < 4; p++) {
                add2(aF[p], pp[p]);
                add2(aO[p], pp[4 + p]);
                add2(aG[p], pp[8 + p]);
            }
            // state update
            float hnew[M_];
            #pragma unroll
            for (int p = 0; p < 4; p++) {
                float f0, f1, o0, o1, g0, g1;
                unpack2(aF[p], f0, f1);
                unpack2(aO[p], o0, o1);
                unpack2(aG[p], g0, g1);
                const int m0 = 2 * p, m1 = 2 * p + 1;
                c[m0] = sigmoidf_(f0) * c[m0] + ig[m0] * tanhf_(g0);
                c[m1] = sigmoidf_(f1) * c[m1] + ig[m1] * tanhf_(g1);
                hnew[m0] = sigmoidf_(o0) * tanhf_(c[m0]);
                hnew[m1] = sigmoidf_(o1) * tanhf_(c[m1]);
            }
            #pragma unroll
            for (int m = 0; m < M_; m++) h_s[col * HS_STRIDE + m] = hnew[m];
        } else {
            // stage x for t+1
            if (t + 1 < T_) {
                const int m = col >> 5, k = col & 31;
                x_s[k * M_ + m] = xd[((size_t)(b0 + m) * T_ + (t + 1)) * DD + k];
            }
        }

        __syncthreads();   // h_s(t) and x_s(t+1) published

        // output: out[b0+w][t] = h . W_out + b_out  (group-0 warp w owns m=w)
        if (grp == 0) {
            float acc = 0.0f;
            #pragma unroll
            for (int q = 0; q < 8; q++) {
                const int jj = lane + 32 * q;
                acc = fmaf(h_s[jj * HS_STRIDE + warp], wout[q], acc);
            }
            #pragma unroll
            for (int off = 16; off > 0; off >>= 1)
                acc += __shfl_down_sync(0xffffffffu, acc, off);
            if (lane == 0)
                out[(size_t)(b0 + warp) * T_ + t] = acc + b_out0;
        }
        // next iteration's h_s/p_s writes are fenced by its own first sync
    }
}

extern "C" void kernel_launch(void* const* d_in, const int* in_sizes, int n_in,
                              void* d_out, int out_size) {
    const float* xd     = (const float*)d_in[0];  // x_dynamic [1024,365,32]
    const float* xs     = (const float*)d_in[1];  // x_static  [1024,27]
    const float* Wih    = (const float*)d_in[2];  // [32,768]
    const float* Whh    = (const float*)d_in[3];  // [256,768]
    const float* Wsh    = (const float*)d_in[4];  // [27,256]
    const float* bias   = (const float*)d_in[5];  // [768]
    const float* bias_s = (const float*)d_in[6];  // [256]
    const float* Wout   = (const float*)d_in[7];  // [256,1]
    const float* bout   = (const float*)d_in[8];  // [1]
    float* out = (float*)d_out;                   // [1024,365,1]

    ealstm_kernel<<<CTAS, THREADS>>>(xd, xs, Wih, Whh, Wsh, bias, bias_s,
                                     Wout, bout, out);
}